// round 5
// baseline (speedup 1.0000x reference)
#include <cuda_runtime.h>
#include <math.h>

// MultiStepUnitaryGCN collapses algebraically: star-graph evolution weights are
// Re(exp(-itA)[0,:]) = [cos(t*sqrt(d)), 0, ..., 0]  => per-node MLP:
//   h   = relu(cos(sqrt(d)) * (x @ W1^T) + b1)
//   o   = cos(0.5*sqrt(d)) * (h @ W2^T) + b2
//   out = log_softmax(o, axis=1)
// nbr_mask arrives as int32 [N,16]; neighbors unused.
//
// R4 -> R5: fix inline-asm operand index in ffma2 (%3 -> %0 with "+l" rw
// constraint); design unchanged: packed fp32 via PTX fma.rn.f32x2 (SASS
// FFMA2), row pairs, transposed swizzled x/h tile for 64-bit broadcast LDS.

#define N_NODES 50000
#define KNBR    16
#define CIN     128
#define CHID    128
#define COUT    64
#define TM      64
#define NTHREADS 256
#define W1S 132            // W1t row stride (floats)
#define W2S 70             // W2t row stride (floats)
#define XS  66             // transposed x/h tile row stride (floats, even)

// smem (floats):
//  sW1t : 128*132 = 16896   phase B alias: sW2t = [0,8960), sO = [8960,13056)
//  sXt  : 128*66  =  8448   (x transposed; reused for h transposed)
//  sC1,sC2 : 64 each; sB1 : 128; sB2 : 64
#define SMEM_FLOATS (CIN*W1S + CIN*XS + 2*TM + CHID + COUT)
#define SMEM_BYTES  (SMEM_FLOATS * 4)

typedef unsigned long long u64;

__device__ __forceinline__ u64 pack2(float v) {          // (v, v)
    u64 r; asm("mov.b64 %0, {%1, %1};" : "=l"(r) : "f"(v)); return r;
}
__device__ __forceinline__ u64 packf2(float x, float y) { // (x, y)
    u64 r; asm("mov.b64 %0, {%1, %2};" : "=l"(r) : "f"(x), "f"(y)); return r;
}
__device__ __forceinline__ float2 unpack2(u64 v) {
    float2 f; asm("mov.b64 {%0, %1}, %2;" : "=f"(f.x), "=f"(f.y) : "l"(v)); return f;
}
__device__ __forceinline__ void ffma2(u64& d, u64 a, u64 b) {
    asm("fma.rn.f32x2 %0, %1, %2, %0;" : "+l"(d) : "l"(a), "l"(b));
}

// pair-slot offset inside transposed tile (low bit selects row within pair);
// XOR swizzle on the pair index, parameterized by k>>2, keeps scatter-stores
// at most 2-way conflicted while loads (warp-uniform) stay broadcasts.
__device__ __forceinline__ int xsw(int k, int pr) {
    return k * XS + ((pr ^ ((k >> 2) & 31)) << 1);
}

__global__ void __launch_bounds__(NTHREADS, 2)
fused_gcn_kernel(const float* __restrict__ x,
                 const int* __restrict__ mask,
                 const float* __restrict__ W1,
                 const float* __restrict__ b1,
                 const float* __restrict__ W2,
                 const float* __restrict__ b2,
                 float* __restrict__ out)
{
    extern __shared__ float smem[];
    float* sW1t = smem;                       // 16896
    float* sW2t = smem;                       // alias (phase B), 8960
    float* sO   = smem + CHID * W2S;          // alias (phase B), 4096
    float* sXt  = smem + CIN * W1S;           // 8448 (x^T, later h^T)
    float* sC1  = sXt + CIN * XS;
    float* sC2  = sC1 + TM;
    float* sB1  = sC2 + TM;
    float* sB2  = sB1 + CHID;

    const int tid  = threadIdx.x;
    const int row0 = blockIdx.x * TM;

    // ---- stage W1 transposed: sW1t[k*W1S + c] = W1[c*CIN + k]
    for (int idx = tid; idx < CHID * CIN; idx += NTHREADS) {
        int c = idx >> 7;
        int k = idx & 127;
        sW1t[k * W1S + c] = W1[idx];
    }
    if (tid < CHID) sB1[tid] = b1[tid];
    if (tid < COUT) sB2[tid] = b2[tid];

    // ---- stage x tile TRANSPOSED with swizzle (float4 gmem reads, coalesced)
    {
        const float4* xv = (const float4*)x;
        for (int idx = tid; idx < TM * (CIN / 4); idx += NTHREADS) {
            int r = idx >> 5;              // CIN/4 == 32
            int q = idx & 31;              // k-quad
            float4 v = make_float4(0.f, 0.f, 0.f, 0.f);
            if (row0 + r < N_NODES) v = xv[(row0 + r) * (CIN / 4) + q];
            int k0 = q * 4;
            int base = xsw(k0, r >> 1) + (r & 1);   // (k0+j)>>2 == q for j<4
            sXt[base]          = v.x;
            sXt[base + XS]     = v.y;
            sXt[base + 2 * XS] = v.z;
            sXt[base + 3 * XS] = v.w;
        }
    }

    // ---- degree -> cos factors (mask int32 0/1)
    if (tid < TM) {
        int r = row0 + tid;
        float c1 = 0.f, c2 = 0.f;
        if (r < N_NODES) {
            const int4* mp = (const int4*)(mask + (size_t)r * KNBR);
            int4 m0 = mp[0], m1 = mp[1], m2 = mp[2], m3 = mp[3];
            int d = m0.x + m0.y + m0.z + m0.w + m1.x + m1.y + m1.z + m1.w
                  + m2.x + m2.y + m2.z + m2.w + m3.x + m3.y + m3.z + m3.w;
            float sd = sqrtf((float)d);
            c1 = cosf(sd);
            c2 = cosf(0.5f * sd);
        }
        sC1[tid] = c1;
        sC2[tid] = c2;
    }
    __syncthreads();

    const int warp = tid >> 5;     // row group: 8 rows = 4 pairs per warp
    const int lane = tid & 31;
    const int pr0  = warp * 4;     // first pair index of this warp

    // ---- GEMM1: h[64][128] = x @ W1^T ; tile = 4 row-pairs x 4 cols (FFMA2)
    u64 acc[4][4];
#pragma unroll
    for (int p = 0; p < 4; ++p)
#pragma unroll
        for (int c = 0; c < 4; ++c) acc[p][c] = 0ull;

    {
        const float* wrow = sW1t + lane * 4;
#pragma unroll 2
        for (int kq = 0; kq < CIN; kq += 4) {
            u64 Bp[4][4];
#pragma unroll
            for (int j = 0; j < 4; ++j) {
                float4 b = *(const float4*)(wrow + (kq + j) * W1S);
                Bp[j][0] = pack2(b.x); Bp[j][1] = pack2(b.y);
                Bp[j][2] = pack2(b.z); Bp[j][3] = pack2(b.w);
            }
#pragma unroll
            for (int p = 0; p < 4; ++p) {
#pragma unroll
                for (int j = 0; j < 4; ++j) {
                    u64 a = *(const u64*)(sXt + xsw(kq + j, pr0 + p));
                    ffma2(acc[p][0], a, Bp[j][0]);
                    ffma2(acc[p][1], a, Bp[j][1]);
                    ffma2(acc[p][2], a, Bp[j][2]);
                    ffma2(acc[p][3], a, Bp[j][3]);
                }
            }
        }
    }
    __syncwarp();   // rows are warp-private in sXt; wait own warp's reads

    // ---- epilogue1: h = relu(c1*acc + b1) -> sXt (transposed, paired stores)
    {
        float4 bb = *(const float4*)(sB1 + lane * 4);
        float bc[4] = {bb.x, bb.y, bb.z, bb.w};
#pragma unroll
        for (int p = 0; p < 4; ++p) {
            int r0 = warp * 8 + 2 * p;
            float c1a = sC1[r0], c1b = sC1[r0 + 1];
#pragma unroll
            for (int c = 0; c < 4; ++c) {
                float2 v = unpack2(acc[p][c]);
                float h0 = fmaxf(fmaf(c1a, v.x, bc[c]), 0.f);
                float h1 = fmaxf(fmaf(c1b, v.y, bc[c]), 0.f);
                int k = lane * 4 + c;
                *(u64*)(sXt + xsw(k, pr0 + p)) = packf2(h0, h1);
            }
        }
    }
    __syncthreads();   // all warps done with sW1t reads

    // ---- restage W2 transposed into alias: sW2t[k*W2S + c] = W2[c*CHID + k]
    for (int idx = tid; idx < COUT * CHID; idx += NTHREADS) {
        int c = idx >> 7;
        int k = idx & 127;
        sW2t[k * W2S + c] = W2[idx];
    }
    __syncthreads();

    // ---- GEMM2: o[64][64] = h @ W2^T ; tile = 4 row-pairs x 2 cols (FFMA2)
    u64 acc2[4][2];
#pragma unroll
    for (int p = 0; p < 4; ++p) { acc2[p][0] = 0ull; acc2[p][1] = 0ull; }

    {
        const float* wrow = sW2t + lane * 2;
#pragma unroll 2
        for (int kq = 0; kq < CHID; kq += 4) {
            u64 Bp[4][2];
#pragma unroll
            for (int j = 0; j < 4; ++j) {
                float2 b = *(const float2*)(wrow + (kq + j) * W2S);
                Bp[j][0] = pack2(b.x); Bp[j][1] = pack2(b.y);
            }
#pragma unroll
            for (int p = 0; p < 4; ++p) {
#pragma unroll
                for (int j = 0; j < 4; ++j) {
                    u64 a = *(const u64*)(sXt + xsw(kq + j, pr0 + p));
                    ffma2(acc2[p][0], a, Bp[j][0]);
                    ffma2(acc2[p][1], a, Bp[j][1]);
                }
            }
        }
    }

    // ---- epilogue2: o = c2*acc2 + b2 -> sO (disjoint from sW2t region)
#pragma unroll
    for (int p = 0; p < 4; ++p) {
        int r0 = warp * 8 + 2 * p;
        float c2a = sC2[r0], c2b = sC2[r0 + 1];
#pragma unroll
        for (int c = 0; c < 2; ++c) {
            float2 v = unpack2(acc2[p][c]);
            float bv = sB2[lane * 2 + c];
            sO[r0 * COUT + lane * 2 + c]        = fmaf(c2a, v.x, bv);
            sO[(r0 + 1) * COUT + lane * 2 + c]  = fmaf(c2b, v.y, bv);
        }
    }
    __syncwarp();   // each warp reads back only its own 8 rows

    // ---- log_softmax per row; warp handles its 8 rows, 2 cols per lane
#pragma unroll
    for (int j = 0; j < 8; ++j) {
        int r = warp * 8 + j;
        int grow = row0 + r;
        if (grow >= N_NODES) continue;   // uniform across warp
        float v0 = sO[r * COUT + lane];
        float v1 = sO[r * COUT + lane + 32];
        float m = fmaxf(v0, v1);
#pragma unroll
        for (int off = 16; off; off >>= 1)
            m = fmaxf(m, __shfl_xor_sync(0xffffffffu, m, off));
        float s = expf(v0 - m) + expf(v1 - m);
#pragma unroll
        for (int off = 16; off; off >>= 1)
            s += __shfl_xor_sync(0xffffffffu, s, off);
        float lse = m + logf(s);
        out[(size_t)grow * COUT + lane]      = v0 - lse;
        out[(size_t)grow * COUT + lane + 32] = v1 - lse;
    }
}

extern "C" void kernel_launch(void* const* d_in, const int* in_sizes, int n_in,
                              void* d_out, int out_size)
{
    const float* x    = (const float*)d_in[0];
    // d_in[1] = neighbors (unused)
    const int*   mask = (const int*)d_in[2];
    const float* W1   = (const float*)d_in[3];
    const float* b1   = (const float*)d_in[4];
    const float* W2   = (const float*)d_in[5];
    const float* b2   = (const float*)d_in[6];
    float*       out  = (float*)d_out;

    cudaFuncSetAttribute(fused_gcn_kernel,
                         cudaFuncAttributeMaxDynamicSharedMemorySize, SMEM_BYTES);

    const int grid = (N_NODES + TM - 1) / TM;   // 782
    fused_gcn_kernel<<<grid, NTHREADS, SMEM_BYTES>>>(x, mask, W1, b1, W2, b2, out);
}

// round 6
// speedup vs baseline: 2.2172x; 2.2172x over previous
#include <cuda_runtime.h>
#include <math.h>

// MultiStepUnitaryGCN collapses algebraically: star-graph evolution weights are
// Re(exp(-itA)[0,:]) = [cos(t*sqrt(d)), 0, ..., 0]  => per-node MLP:
//   h   = relu(cos(sqrt(d)) * (x @ W1^T) + b1)
//   o   = cos(0.5*sqrt(d)) * (h @ W2^T) + b2
//   out = log_softmax(o, axis=1)
// nbr_mask arrives as int32 [N,16]; neighbors unused.
//
// R5 -> R6: FFMA2 path abandoned (ptxas emulates fma.rn.f32x2 -> 2xFFMA+MOVs).
// Back to R3 scalar design; occupancy fix: W1t/W2t staged in 64-k-row halves
// through ONE 8448-float buffer -> smem ~68KB/CTA -> 3 CTAs/SM (24 warps).

#define N_NODES 50000
#define KNBR    16
#define CIN     128
#define CHID    128
#define COUT    64
#define TM      64
#define NTHREADS 256
#define KH      64          // k-rows per staging half
#define W1S 132             // W-buffer row stride for GEMM1 (floats)
#define W2S 66              // W-buffer row stride for GEMM2 (floats)

// smem (floats):
//  sW  : KH * W1S = 8448   (W1t half / W2t half / final sO overlay)
//  sX  : TM * CIN = 8192   (x tile; reused for h)
//  sC1,sC2 : 64 each; sB1 : 128; sB2 : 64
#define SMEM_FLOATS (KH*W1S + TM*CIN + 2*TM + CHID + COUT)
#define SMEM_BYTES  (SMEM_FLOATS * 4)

__global__ void __launch_bounds__(NTHREADS, 3)
fused_gcn_kernel(const float* __restrict__ x,
                 const int* __restrict__ mask,
                 const float* __restrict__ W1,
                 const float* __restrict__ b1,
                 const float* __restrict__ W2,
                 const float* __restrict__ b2,
                 float* __restrict__ out)
{
    extern __shared__ float smem[];
    float* sW  = smem;                 // 8448 floats (W half buffer, sO overlay)
    float* sO  = smem;                 // 4096 floats (phase-final overlay)
    float* sX  = smem + KH * W1S;      // 8192 floats
    float* sC1 = sX + TM * CIN;
    float* sC2 = sC1 + TM;
    float* sB1 = sC2 + TM;
    float* sB2 = sB1 + CHID;

    const int tid  = threadIdx.x;
    const int row0 = blockIdx.x * TM;

    // ---- stage W1t half 0: sW[kk*W1S + c] = W1[c*CIN + kk]
    for (int idx = tid; idx < CHID * KH; idx += NTHREADS) {
        int c  = idx >> 6;
        int kk = idx & (KH - 1);
        sW[kk * W1S + c] = W1[c * CIN + kk];
    }
    if (tid < CHID) sB1[tid] = b1[tid];
    if (tid < COUT) sB2[tid] = b2[tid];

    // ---- stage x tile (float4, zero-pad OOB rows)
    {
        const float4* xv  = (const float4*)x;
        float4*       sXv = (float4*)sX;
        const int base = row0 * (CIN / 4);
        for (int idx = tid; idx < TM * (CIN / 4); idx += NTHREADS) {
            int r = idx / (CIN / 4);
            float4 v = make_float4(0.f, 0.f, 0.f, 0.f);
            if (row0 + r < N_NODES) v = xv[base + idx];
            sXv[idx] = v;
        }
    }

    // ---- degree -> cos factors (mask int32 0/1)
    if (tid < TM) {
        int r = row0 + tid;
        float c1 = 0.f, c2 = 0.f;
        if (r < N_NODES) {
            const int4* mp = (const int4*)(mask + (size_t)r * KNBR);
            int4 m0 = mp[0], m1 = mp[1], m2 = mp[2], m3 = mp[3];
            int d = m0.x + m0.y + m0.z + m0.w + m1.x + m1.y + m1.z + m1.w
                  + m2.x + m2.y + m2.z + m2.w + m3.x + m3.y + m3.z + m3.w;
            float sd = sqrtf((float)d);
            c1 = cosf(sd);
            c2 = cosf(0.5f * sd);
        }
        sC1[tid] = c1;
        sC2[tid] = c2;
    }
    __syncthreads();

    const int warp = tid >> 5;     // row group (8 rows per warp)
    const int lane = tid & 31;
    const float* aBase = sX + (warp * 8) * CIN;

    // ---- GEMM1: h[64][128] = x @ W1^T ; thread tile 8 rows x 4 cols
    float4 acc[8];
#pragma unroll
    for (int i = 0; i < 8; ++i) acc[i] = make_float4(0.f, 0.f, 0.f, 0.f);

#pragma unroll 1
    for (int kh = 0; kh < 2; ++kh) {
        const int kbase = kh * KH;
#pragma unroll 2
        for (int kq = 0; kq < KH; kq += 4) {
            const float* bp = sW + kq * W1S + lane * 4;
            float4 b0  = *(const float4*)(bp);
            float4 b1v = *(const float4*)(bp + W1S);
            float4 b2v = *(const float4*)(bp + 2 * W1S);
            float4 b3v = *(const float4*)(bp + 3 * W1S);
#pragma unroll
            for (int i = 0; i < 8; ++i) {
                float4 a = *(const float4*)(aBase + i * CIN + kbase + kq);
                acc[i].x = fmaf(a.x, b0.x, acc[i].x);
                acc[i].y = fmaf(a.x, b0.y, acc[i].y);
                acc[i].z = fmaf(a.x, b0.z, acc[i].z);
                acc[i].w = fmaf(a.x, b0.w, acc[i].w);
                acc[i].x = fmaf(a.y, b1v.x, acc[i].x);
                acc[i].y = fmaf(a.y, b1v.y, acc[i].y);
                acc[i].z = fmaf(a.y, b1v.z, acc[i].z);
                acc[i].w = fmaf(a.y, b1v.w, acc[i].w);
                acc[i].x = fmaf(a.z, b2v.x, acc[i].x);
                acc[i].y = fmaf(a.z, b2v.y, acc[i].y);
                acc[i].z = fmaf(a.z, b2v.z, acc[i].z);
                acc[i].w = fmaf(a.z, b2v.w, acc[i].w);
                acc[i].x = fmaf(a.w, b3v.x, acc[i].x);
                acc[i].y = fmaf(a.w, b3v.y, acc[i].y);
                acc[i].z = fmaf(a.w, b3v.z, acc[i].z);
                acc[i].w = fmaf(a.w, b3v.w, acc[i].w);
            }
        }
        __syncthreads();                 // all warps done reading this W half
        if (kh == 0) {
            // stage W1t half 1
            for (int idx = tid; idx < CHID * KH; idx += NTHREADS) {
                int c  = idx >> 6;
                int kk = idx & (KH - 1);
                sW[kk * W1S + c] = W1[c * CIN + KH + kk];
            }
            __syncthreads();
        }
    }

    // ---- epilogue1: h = relu(c1*acc + b1) -> sX (each warp its own 8 rows)
    {
        float4 bb = *(const float4*)(sB1 + lane * 4);
#pragma unroll
        for (int i = 0; i < 8; ++i) {
            int r = warp * 8 + i;
            float c1 = sC1[r];
            float4 h;
            h.x = fmaxf(fmaf(c1, acc[i].x, bb.x), 0.f);
            h.y = fmaxf(fmaf(c1, acc[i].y, bb.y), 0.f);
            h.z = fmaxf(fmaf(c1, acc[i].z, bb.z), 0.f);
            h.w = fmaxf(fmaf(c1, acc[i].w, bb.w), 0.f);
            *(float4*)(sX + r * CIN + lane * 4) = h;
        }
    }
    // stage W2t half 0: sW[kk*W2S + c] = W2[c*CHID + kk]
    for (int idx = tid; idx < COUT * KH; idx += NTHREADS) {
        int c  = idx >> 6;
        int kk = idx & (KH - 1);
        sW[kk * W2S + c] = W2[c * CHID + kk];
    }
    __syncthreads();

    // ---- GEMM2: o[64][64] = h @ W2^T ; thread tile 8 rows x 2 cols
    float2 acc2[8];
#pragma unroll
    for (int i = 0; i < 8; ++i) acc2[i] = make_float2(0.f, 0.f);

#pragma unroll 1
    for (int kh = 0; kh < 2; ++kh) {
        const int kbase = kh * KH;
#pragma unroll 2
        for (int kq = 0; kq < KH; kq += 4) {
            const float* cp = sW + kq * W2S + lane * 2;
            float2 c0  = *(const float2*)(cp);
            float2 c1v = *(const float2*)(cp + W2S);
            float2 c2v = *(const float2*)(cp + 2 * W2S);
            float2 c3v = *(const float2*)(cp + 3 * W2S);
#pragma unroll
            for (int i = 0; i < 8; ++i) {
                float4 a = *(const float4*)(aBase + i * CIN + kbase + kq);
                acc2[i].x = fmaf(a.x, c0.x, acc2[i].x);
                acc2[i].y = fmaf(a.x, c0.y, acc2[i].y);
                acc2[i].x = fmaf(a.y, c1v.x, acc2[i].x);
                acc2[i].y = fmaf(a.y, c1v.y, acc2[i].y);
                acc2[i].x = fmaf(a.z, c2v.x, acc2[i].x);
                acc2[i].y = fmaf(a.z, c2v.y, acc2[i].y);
                acc2[i].x = fmaf(a.w, c3v.x, acc2[i].x);
                acc2[i].y = fmaf(a.w, c3v.y, acc2[i].y);
            }
        }
        __syncthreads();                 // all warps done reading this W half
        if (kh == 0) {
            // stage W2t half 1
            for (int idx = tid; idx < COUT * KH; idx += NTHREADS) {
                int c  = idx >> 6;
                int kk = idx & (KH - 1);
                sW[kk * W2S + c] = W2[c * CHID + KH + kk];
            }
            __syncthreads();
        }
    }

    // ---- epilogue2: o = c2*acc2 + b2 -> sO (overlays sW; all reads drained)
#pragma unroll
    for (int i = 0; i < 8; ++i) {
        int r = warp * 8 + i;
        float c2v = sC2[r];
        sO[r * COUT + lane * 2 + 0] = fmaf(c2v, acc2[i].x, sB2[lane * 2 + 0]);
        sO[r * COUT + lane * 2 + 1] = fmaf(c2v, acc2[i].y, sB2[lane * 2 + 1]);
    }
    __syncwarp();   // each warp reads back only its own 8 rows

    // ---- log_softmax per row; warp handles its 8 rows, 2 cols per lane
#pragma unroll
    for (int j = 0; j < 8; ++j) {
        int r = warp * 8 + j;
        int grow = row0 + r;
        if (grow >= N_NODES) continue;   // uniform across warp
        float v0 = sO[r * COUT + lane];
        float v1 = sO[r * COUT + lane + 32];
        float m = fmaxf(v0, v1);
#pragma unroll
        for (int off = 16; off; off >>= 1)
            m = fmaxf(m, __shfl_xor_sync(0xffffffffu, m, off));
        float s = expf(v0 - m) + expf(v1 - m);
#pragma unroll
        for (int off = 16; off; off >>= 1)
            s += __shfl_xor_sync(0xffffffffu, s, off);
        float lse = m + logf(s);
        out[(size_t)grow * COUT + lane]      = v0 - lse;
        out[(size_t)grow * COUT + lane + 32] = v1 - lse;
    }
}

extern "C" void kernel_launch(void* const* d_in, const int* in_sizes, int n_in,
                              void* d_out, int out_size)
{
    const float* x    = (const float*)d_in[0];
    // d_in[1] = neighbors (unused)
    const int*   mask = (const int*)d_in[2];
    const float* W1   = (const float*)d_in[3];
    const float* b1   = (const float*)d_in[4];
    const float* W2   = (const float*)d_in[5];
    const float* b2   = (const float*)d_in[6];
    float*       out  = (float*)d_out;

    cudaFuncSetAttribute(fused_gcn_kernel,
                         cudaFuncAttributeMaxDynamicSharedMemorySize, SMEM_BYTES);

    const int grid = (N_NODES + TM - 1) / TM;   // 782
    fused_gcn_kernel<<<grid, NTHREADS, SMEM_BYTES>>>(x, mask, W1, b1, W2, b2, out);
}

// round 8
// speedup vs baseline: 3.4564x; 1.5589x over previous
#include <cuda_runtime.h>
#include <math.h>
#include <stdint.h>

// MultiStepUnitaryGCN collapses algebraically to a per-node MLP:
//   h   = relu(cos(sqrt(d)) * (x @ W1^T) + b1)
//   o   = cos(0.5*sqrt(d)) * (h @ W2^T) + b2
//   out = log_softmax(o, axis=1)
// (star-evolution weights are [cos(t*sqrt(d)),0,...]; neighbors unused;
//  nbr_mask arrives as int32 [N,16]).
//
// R7 -> R8: tcgen05 is rejected (harness targets plain sm_103, no 'a'
// features). Use baseline-PTX mma.sync m16n8k8 tf32 (HMMA fallback) instead.
// Row-major stride-132 tiles are conflict-free for BOTH A and B fragment
// loads; operands converted to tf32 at staging; fp32 accumulate.

#define N_NODES 50000
#define KNBR    16
#define CIN     128
#define CHID    128
#define COUT    64
#define TM      128
#define THREADS 256
#define AS      132      // tile row stride (32-bit words)

// smem words (uint32/float):
//  sA  [128*132]=16896  x tile as tf32, later h as tf32
//  sW1 [128*132]=16896  W1 as tf32          (overlay: sO 128*64 floats)
//  sW2 [ 64*132]= 8448  W2 as tf32
//  sC1[128] sC2[128] sB1[128] sB2[64]
#define SMEM_WORDS (16896 + 16896 + 8448 + 128 + 128 + 128 + 64)
#define SMEM_BYTES (SMEM_WORDS * 4)

__device__ __forceinline__ uint32_t f2tf(float f) {
    uint32_t u; asm("cvt.rna.tf32.f32 %0, %1;" : "=r"(u) : "f"(f)); return u;
}

__device__ __forceinline__ void mma8(float* d, const uint32_t* a,
                                     const uint32_t* b) {
    asm volatile(
        "mma.sync.aligned.m16n8k8.row.col.f32.tf32.tf32.f32 "
        "{%0,%1,%2,%3}, {%4,%5,%6,%7}, {%8,%9}, {%0,%1,%2,%3};"
        : "+f"(d[0]), "+f"(d[1]), "+f"(d[2]), "+f"(d[3])
        : "r"(a[0]), "r"(a[1]), "r"(a[2]), "r"(a[3]), "r"(b[0]), "r"(b[1]));
}

__global__ void __launch_bounds__(THREADS, 1)
gcn_mma_kernel(const float* __restrict__ x, const int* __restrict__ mask,
               const float* __restrict__ W1, const float* __restrict__ b1,
               const float* __restrict__ W2, const float* __restrict__ b2,
               float* __restrict__ out)
{
    extern __shared__ uint32_t smem[];
    uint32_t* sA  = smem;             // 16896
    uint32_t* sW1 = smem + 16896;     // 16896
    uint32_t* sW2 = smem + 33792;     // 8448
    float*    sO  = (float*)(smem + 16896);   // overlay of sW1 (8192 floats)
    float*    sC1 = (float*)(smem + 42240);
    float*    sC2 = sC1 + 128;
    float*    sB1 = sC2 + 128;
    float*    sB2 = sB1 + 128;

    const int tid  = threadIdx.x;
    const int lane = tid & 31;
    const int warp = tid >> 5;
    const int wr   = warp >> 1;        // 0..3 : 32-row group
    const int wc   = warp & 1;         // 0..1 : col half
    const int m0   = wr * 32;
    const int row0 = blockIdx.x * TM;

    // ---- stage x tile as tf32 (zero-pad OOB rows)
    for (int idx = tid; idx < TM * 32; idx += THREADS) {
        int r = idx >> 5, q = idx & 31;
        float4 v = make_float4(0.f, 0.f, 0.f, 0.f);
        if (row0 + r < N_NODES)
            v = *(const float4*)(x + (size_t)(row0 + r) * CIN + q * 4);
        uint4 u = make_uint4(f2tf(v.x), f2tf(v.y), f2tf(v.z), f2tf(v.w));
        *(uint4*)(sA + r * AS + q * 4) = u;
    }
    // ---- stage W1 [128x128] as tf32, row-major
    for (int idx = tid; idx < CHID * 32; idx += THREADS) {
        int r = idx >> 5, q = idx & 31;
        float4 v = *(const float4*)(W1 + r * CIN + q * 4);
        *(uint4*)(sW1 + r * AS + q * 4) =
            make_uint4(f2tf(v.x), f2tf(v.y), f2tf(v.z), f2tf(v.w));
    }
    // ---- stage W2 [64x128] as tf32
    for (int idx = tid; idx < COUT * 32; idx += THREADS) {
        int r = idx >> 5, q = idx & 31;
        float4 v = *(const float4*)(W2 + r * CHID + q * 4);
        *(uint4*)(sW2 + r * AS + q * 4) =
            make_uint4(f2tf(v.x), f2tf(v.y), f2tf(v.z), f2tf(v.w));
    }
    if (tid < CHID) sB1[tid] = b1[tid];
    if (tid < COUT) sB2[tid] = b2[tid];

    // ---- degree -> cos factors
    if (tid < TM) {
        int r = row0 + tid;
        float c1 = 0.f, c2 = 0.f;
        if (r < N_NODES) {
            const int4* mp = (const int4*)(mask + (size_t)r * KNBR);
            int4 m0v = mp[0], m1v = mp[1], m2v = mp[2], m3v = mp[3];
            int d = m0v.x + m0v.y + m0v.z + m0v.w + m1v.x + m1v.y + m1v.z + m1v.w
                  + m2v.x + m2v.y + m2v.z + m2v.w + m3v.x + m3v.y + m3v.z + m3v.w;
            float sd = sqrtf((float)d);
            c1 = cosf(sd);
            c2 = cosf(0.5f * sd);
        }
        sC1[tid] = c1;
        sC2[tid] = c2;
    }
    __syncthreads();

    // ---- GEMM1: 128x128 = X @ W1^T ; warp tile 32x64
    float d1[2][8][4];
#pragma unroll
    for (int mt = 0; mt < 2; ++mt)
#pragma unroll
        for (int nt = 0; nt < 8; ++nt)
#pragma unroll
            for (int j = 0; j < 4; ++j) d1[mt][nt][j] = 0.f;

#pragma unroll 2
    for (int k0 = 0; k0 < CIN; k0 += 8) {
        uint32_t a[2][4];
#pragma unroll
        for (int mt = 0; mt < 2; ++mt) {
            int r = m0 + mt * 16 + (lane >> 2);
            int c = k0 + (lane & 3);
            a[mt][0] = sA[r * AS + c];
            a[mt][1] = sA[(r + 8) * AS + c];
            a[mt][2] = sA[r * AS + c + 4];
            a[mt][3] = sA[(r + 8) * AS + c + 4];
        }
#pragma unroll
        for (int nt = 0; nt < 8; ++nt) {
            int col = wc * 64 + nt * 8 + (lane >> 2);
            uint32_t b[2];
            b[0] = sW1[col * AS + k0 + (lane & 3)];
            b[1] = sW1[col * AS + k0 + (lane & 3) + 4];
            mma8(d1[0][nt], a[0], b);
            mma8(d1[1][nt], a[1], b);
        }
    }
    __syncthreads();   // all warps done reading x from sA

    // ---- epilogue1: h = relu(c1*d + b1) -> sA (as tf32)
#pragma unroll
    for (int mt = 0; mt < 2; ++mt) {
        int r = m0 + mt * 16 + (lane >> 2);
        float c1a = sC1[r], c1b = sC1[r + 8];
#pragma unroll
        for (int nt = 0; nt < 8; ++nt) {
            int c = wc * 64 + nt * 8 + 2 * (lane & 3);
            float bx = sB1[c], by = sB1[c + 1];
            uint32_t h00 = f2tf(fmaxf(fmaf(c1a, d1[mt][nt][0], bx), 0.f));
            uint32_t h01 = f2tf(fmaxf(fmaf(c1a, d1[mt][nt][1], by), 0.f));
            uint32_t h10 = f2tf(fmaxf(fmaf(c1b, d1[mt][nt][2], bx), 0.f));
            uint32_t h11 = f2tf(fmaxf(fmaf(c1b, d1[mt][nt][3], by), 0.f));
            *(uint2*)(sA + r * AS + c)       = make_uint2(h00, h01);
            *(uint2*)(sA + (r + 8) * AS + c) = make_uint2(h10, h11);
        }
    }
    __syncthreads();

    // ---- GEMM2: 128x64 = H @ W2^T ; warp tile 32x32
    float d2[2][4][4];
#pragma unroll
    for (int mt = 0; mt < 2; ++mt)
#pragma unroll
        for (int nt = 0; nt < 4; ++nt)
#pragma unroll
            for (int j = 0; j < 4; ++j) d2[mt][nt][j] = 0.f;

#pragma unroll 2
    for (int k0 = 0; k0 < CHID; k0 += 8) {
        uint32_t a[2][4];
#pragma unroll
        for (int mt = 0; mt < 2; ++mt) {
            int r = m0 + mt * 16 + (lane >> 2);
            int c = k0 + (lane & 3);
            a[mt][0] = sA[r * AS + c];
            a[mt][1] = sA[(r + 8) * AS + c];
            a[mt][2] = sA[r * AS + c + 4];
            a[mt][3] = sA[(r + 8) * AS + c + 4];
        }
#pragma unroll
        for (int nt = 0; nt < 4; ++nt) {
            int col = wc * 32 + nt * 8 + (lane >> 2);
            uint32_t b[2];
            b[0] = sW2[col * AS + k0 + (lane & 3)];
            b[1] = sW2[col * AS + k0 + (lane & 3) + 4];
            mma8(d2[0][nt], a[0], b);
            mma8(d2[1][nt], a[1], b);
        }
    }
    __syncthreads();   // sW1 reads long done; safe to overlay sO

    // ---- epilogue2: o = c2*d + b2 -> sO [128][64]
#pragma unroll
    for (int mt = 0; mt < 2; ++mt) {
        int r = m0 + mt * 16 + (lane >> 2);
        float c2a = sC2[r], c2b = sC2[r + 8];
#pragma unroll
        for (int nt = 0; nt < 4; ++nt) {
            int c = wc * 32 + nt * 8 + 2 * (lane & 3);
            float bx = sB2[c], by = sB2[c + 1];
            *(float2*)(sO + r * COUT + c) =
                make_float2(fmaf(c2a, d2[mt][nt][0], bx),
                            fmaf(c2a, d2[mt][nt][1], by));
            *(float2*)(sO + (r + 8) * COUT + c) =
                make_float2(fmaf(c2b, d2[mt][nt][2], bx),
                            fmaf(c2b, d2[mt][nt][3], by));
        }
    }
    __syncthreads();

    // ---- log_softmax: 2 threads per row (32 cols each), shfl-combine
    {
        int r    = tid >> 1;
        int half = tid & 1;
        const float* op = sO + r * COUT + half * 32;
        float v[32];
#pragma unroll
        for (int j = 0; j < 32; j += 4) {
            float4 t = *(const float4*)(op + j);
            v[j] = t.x; v[j + 1] = t.y; v[j + 2] = t.z; v[j + 3] = t.w;
        }
        float m = v[0];
#pragma unroll
        for (int j = 1; j < 32; ++j) m = fmaxf(m, v[j]);
        m = fmaxf(m, __shfl_xor_sync(0xffffffffu, m, 1));
        float s = 0.f;
#pragma unroll
        for (int j = 0; j < 32; ++j) s += expf(v[j] - m);
        s += __shfl_xor_sync(0xffffffffu, s, 1);
        float lse = m + logf(s);

        int grow = row0 + r;
        if (grow < N_NODES) {
            float* dst = out + (size_t)grow * COUT + half * 32;
#pragma unroll
            for (int j = 0; j < 32; j += 4) {
                float4 t = make_float4(v[j] - lse, v[j + 1] - lse,
                                       v[j + 2] - lse, v[j + 3] - lse);
                *(float4*)(dst + j) = t;
            }
        }
    }
}

extern "C" void kernel_launch(void* const* d_in, const int* in_sizes, int n_in,
                              void* d_out, int out_size)
{
    const float* x    = (const float*)d_in[0];
    // d_in[1] = neighbors (unused)
    const int*   mask = (const int*)d_in[2];
    const float* W1   = (const float*)d_in[3];
    const float* b1   = (const float*)d_in[4];
    const float* W2   = (const float*)d_in[5];
    const float* b2   = (const float*)d_in[6];
    float*       out  = (float*)d_out;

    cudaFuncSetAttribute(gcn_mma_kernel,
                         cudaFuncAttributeMaxDynamicSharedMemorySize, SMEM_BYTES);

    const int grid = (N_NODES + TM - 1) / TM;   // 391
    gcn_mma_kernel<<<grid, THREADS, SMEM_BYTES>>>(x, mask, W1, b1, W2, b2, out);
}

// round 9
// speedup vs baseline: 3.6251x; 1.0488x over previous
#include <cuda_runtime.h>
#include <math.h>
#include <stdint.h>

// MultiStepUnitaryGCN collapses algebraically to a per-node MLP:
//   h   = relu(cos(sqrt(d)) * (x @ W1^T) + b1)
//   o   = cos(0.5*sqrt(d)) * (h @ W2^T) + b2
//   out = log_softmax(o, axis=1)
// (star-evolution weights are [cos(t*sqrt(d)),0,...]; neighbors unused;
//  nbr_mask arrives as int32 [N,16]).
//
// R8 -> R9: persistent kernel (grid=148), 512 threads (16 warps), weights
// staged to smem ONCE; GEMM1 A-operand read directly from gmem (L1-served,
// 4x intra-CTA reuse); softmax via register partials + tiny smem combine.
// mma.sync m16n8k8 tf32 fragment mapping identical to the validated R8.

#define N_NODES 50000
#define KNBR    16
#define CIN     128
#define CHID    128
#define COUT    64
#define TM      128
#define THREADS 512
#define NTILES  391
#define GRID    148
#define AS      132      // smem tile row stride (words)

// smem words:
//  sW1 [128*132]=16896  sW2 [64*132]=8448  sH [128*132]=16896
//  sC1[128] sC2[128] sB1[128] sB2[64] sR1[512] sR2[512]
#define SMEM_WORDS (16896 + 8448 + 16896 + 128 + 128 + 128 + 64 + 512 + 512)
#define SMEM_BYTES (SMEM_WORDS * 4)

__device__ __forceinline__ uint32_t f2tf(float f) {
    uint32_t u; asm("cvt.rna.tf32.f32 %0, %1;" : "=r"(u) : "f"(f)); return u;
}

__device__ __forceinline__ void mma8(float* d, const uint32_t* a,
                                     const uint32_t* b) {
    asm volatile(
        "mma.sync.aligned.m16n8k8.row.col.f32.tf32.tf32.f32 "
        "{%0,%1,%2,%3}, {%4,%5,%6,%7}, {%8,%9}, {%0,%1,%2,%3};"
        : "+f"(d[0]), "+f"(d[1]), "+f"(d[2]), "+f"(d[3])
        : "r"(a[0]), "r"(a[1]), "r"(a[2]), "r"(a[3]), "r"(b[0]), "r"(b[1]));
}

__global__ void __launch_bounds__(THREADS, 1)
gcn_mma_kernel(const float* __restrict__ x, const int* __restrict__ mask,
               const float* __restrict__ W1, const float* __restrict__ b1,
               const float* __restrict__ W2, const float* __restrict__ b2,
               float* __restrict__ out)
{
    extern __shared__ uint32_t smem[];
    uint32_t* sW1 = smem;                       // 16896
    uint32_t* sW2 = smem + 16896;               // 8448
    uint32_t* sH  = smem + 25344;               // 16896
    float*    sC1 = (float*)(smem + 42240);     // 128
    float*    sC2 = sC1 + 128;
    float*    sB1 = sC2 + 128;
    float*    sB2 = sB1 + 128;                  // 64
    float*    sR1 = sB2 + 64;                   // 512 (per-row, per-wc max)
    float*    sR2 = sR1 + 512;                  // 512 (per-row, per-wc sum)

    const int tid  = threadIdx.x;
    const int lane = tid & 31;
    const int warp = tid >> 5;                  // 16 warps
    const int wr   = warp >> 2;                 // 0..3  -> 32-row group
    const int wc   = warp & 3;                  // 0..3  -> col quarter
    const int m0   = wr * 32;
    const int lq   = lane >> 2;                 // 0..7
    const int lr   = lane & 3;                  // 0..3

    // ---- stage weights ONCE (tf32), biases
    for (int idx = tid; idx < CHID * 32; idx += THREADS) {
        int r = idx >> 5, q = idx & 31;
        float4 v = *(const float4*)(W1 + r * CIN + q * 4);
        *(uint4*)(sW1 + r * AS + q * 4) =
            make_uint4(f2tf(v.x), f2tf(v.y), f2tf(v.z), f2tf(v.w));
    }
    for (int idx = tid; idx < COUT * 32; idx += THREADS) {
        int r = idx >> 5, q = idx & 31;
        float4 v = *(const float4*)(W2 + r * CHID + q * 4);
        *(uint4*)(sW2 + r * AS + q * 4) =
            make_uint4(f2tf(v.x), f2tf(v.y), f2tf(v.z), f2tf(v.w));
    }
    if (tid < CHID) sB1[tid] = b1[tid];
    if (tid < COUT) sB2[tid] = b2[tid];

    for (int tile = blockIdx.x; tile < NTILES; tile += GRID) {
        const int row0 = tile * TM;

        // ---- per-tile cos factors
        if (tid < TM) {
            int r = row0 + tid;
            float c1 = 0.f, c2 = 0.f;
            if (r < N_NODES) {
                const int4* mp = (const int4*)(mask + (size_t)r * KNBR);
                int4 a = mp[0], b = mp[1], c = mp[2], d4 = mp[3];
                int d = a.x + a.y + a.z + a.w + b.x + b.y + b.z + b.w
                      + c.x + c.y + c.z + c.w + d4.x + d4.y + d4.z + d4.w;
                float sd = sqrtf((float)d);
                c1 = cosf(sd);
                c2 = cosf(0.5f * sd);
            }
            sC1[tid] = c1;
            sC2[tid] = c2;
        }
        __syncthreads();   // cos visible; prev-iter sH/sR reads complete

        // ---- GEMM1: A from GMEM (predicated LDG + tf32 cvt), B from sW1
        float d1[2][4][4];
#pragma unroll
        for (int mt = 0; mt < 2; ++mt)
#pragma unroll
            for (int nt = 0; nt < 4; ++nt)
#pragma unroll
                for (int j = 0; j < 4; ++j) d1[mt][nt][j] = 0.f;

        const float* xp[2][2];
        bool gd[2][2];
#pragma unroll
        for (int mt = 0; mt < 2; ++mt) {
            int r = row0 + m0 + mt * 16 + lq;
            gd[mt][0] = (r < N_NODES);
            gd[mt][1] = (r + 8 < N_NODES);
            xp[mt][0] = x + (size_t)r * CIN + lr;
            xp[mt][1] = x + (size_t)(r + 8) * CIN + lr;
        }

#pragma unroll 4
        for (int k0 = 0; k0 < CIN; k0 += 8) {
            uint32_t a[2][4];
#pragma unroll
            for (int mt = 0; mt < 2; ++mt) {
                a[mt][0] = f2tf(gd[mt][0] ? xp[mt][0][k0]     : 0.f);
                a[mt][1] = f2tf(gd[mt][1] ? xp[mt][1][k0]     : 0.f);
                a[mt][2] = f2tf(gd[mt][0] ? xp[mt][0][k0 + 4] : 0.f);
                a[mt][3] = f2tf(gd[mt][1] ? xp[mt][1][k0 + 4] : 0.f);
            }
#pragma unroll
            for (int nt = 0; nt < 4; ++nt) {
                int col = wc * 32 + nt * 8 + lq;
                uint32_t b[2];
                b[0] = sW1[col * AS + k0 + lr];
                b[1] = sW1[col * AS + k0 + lr + 4];
                mma8(d1[0][nt], a[0], b);
                mma8(d1[1][nt], a[1], b);
            }
        }

        // ---- epilogue1: h = relu(c1*d + b1) -> sH (tf32)
#pragma unroll
        for (int mt = 0; mt < 2; ++mt) {
            int r = m0 + mt * 16 + lq;
            float c1a = sC1[r], c1b = sC1[r + 8];
#pragma unroll
            for (int nt = 0; nt < 4; ++nt) {
                int c = wc * 32 + nt * 8 + 2 * lr;
                float bx = sB1[c], by = sB1[c + 1];
                uint32_t h00 = f2tf(fmaxf(fmaf(c1a, d1[mt][nt][0], bx), 0.f));
                uint32_t h01 = f2tf(fmaxf(fmaf(c1a, d1[mt][nt][1], by), 0.f));
                uint32_t h10 = f2tf(fmaxf(fmaf(c1b, d1[mt][nt][2], bx), 0.f));
                uint32_t h11 = f2tf(fmaxf(fmaf(c1b, d1[mt][nt][3], by), 0.f));
                *(uint2*)(sH + r * AS + c)       = make_uint2(h00, h01);
                *(uint2*)(sH + (r + 8) * AS + c) = make_uint2(h10, h11);
            }
        }
        __syncthreads();

        // ---- GEMM2: A from sH, B from sW2 ; warp tile 32x16
        float d2[2][2][4];
#pragma unroll
        for (int mt = 0; mt < 2; ++mt)
#pragma unroll
            for (int nt = 0; nt < 2; ++nt)
#pragma unroll
                for (int j = 0; j < 4; ++j) d2[mt][nt][j] = 0.f;

#pragma unroll 4
        for (int k0 = 0; k0 < CHID; k0 += 8) {
            uint32_t a[2][4];
#pragma unroll
            for (int mt = 0; mt < 2; ++mt) {
                int r = m0 + mt * 16 + lq;
                a[mt][0] = sH[r * AS + k0 + lr];
                a[mt][1] = sH[(r + 8) * AS + k0 + lr];
                a[mt][2] = sH[r * AS + k0 + lr + 4];
                a[mt][3] = sH[(r + 8) * AS + k0 + lr + 4];
            }
#pragma unroll
            for (int nt = 0; nt < 2; ++nt) {
                int col = wc * 16 + nt * 8 + lq;
                uint32_t b[2];
                b[0] = sW2[col * AS + k0 + lr];
                b[1] = sW2[col * AS + k0 + lr + 4];
                mma8(d2[0][nt], a[0], b);
                mma8(d2[1][nt], a[1], b);
            }
        }

        // ---- epilogue2: o = c2*d + b2 (regs) ; softmax via partials
        float o[2][2][4];
        float rmax[2][2] = {{-1e30f, -1e30f}, {-1e30f, -1e30f}};
#pragma unroll
        for (int mt = 0; mt < 2; ++mt) {
            int r = m0 + mt * 16 + lq;
            float c2a = sC2[r], c2b = sC2[r + 8];
#pragma unroll
            for (int nt = 0; nt < 2; ++nt) {
                int c = wc * 16 + nt * 8 + 2 * lr;
                float bx = sB2[c], by = sB2[c + 1];
                o[mt][nt][0] = fmaf(c2a, d2[mt][nt][0], bx);
                o[mt][nt][1] = fmaf(c2a, d2[mt][nt][1], by);
                o[mt][nt][2] = fmaf(c2b, d2[mt][nt][2], bx);
                o[mt][nt][3] = fmaf(c2b, d2[mt][nt][3], by);
                rmax[mt][0] = fmaxf(rmax[mt][0], fmaxf(o[mt][nt][0], o[mt][nt][1]));
                rmax[mt][1] = fmaxf(rmax[mt][1], fmaxf(o[mt][nt][2], o[mt][nt][3]));
            }
        }
        // reduce over the 4 lanes sharing a row (lane&3), publish per-wc max
#pragma unroll
        for (int mt = 0; mt < 2; ++mt)
#pragma unroll
            for (int i = 0; i < 2; ++i) {
                float m = rmax[mt][i];
                m = fmaxf(m, __shfl_xor_sync(0xffffffffu, m, 1));
                m = fmaxf(m, __shfl_xor_sync(0xffffffffu, m, 2));
                rmax[mt][i] = m;
                int r = m0 + mt * 16 + i * 8 + lq;
                sR1[r * 4 + wc] = m;
            }
        __syncthreads();

        float gmax[2][2], psum[2][2];
#pragma unroll
        for (int mt = 0; mt < 2; ++mt)
#pragma unroll
            for (int i = 0; i < 2; ++i) {
                int r = m0 + mt * 16 + i * 8 + lq;
                const float4 mv = *(const float4*)(sR1 + r * 4);
                gmax[mt][i] = fmaxf(fmaxf(mv.x, mv.y), fmaxf(mv.z, mv.w));
            }
#pragma unroll
        for (int mt = 0; mt < 2; ++mt) {
            float s0 = 0.f, s1 = 0.f;
#pragma unroll
            for (int nt = 0; nt < 2; ++nt) {
                s0 += expf(o[mt][nt][0] - gmax[mt][0]);
                s0 += expf(o[mt][nt][1] - gmax[mt][0]);
                s1 += expf(o[mt][nt][2] - gmax[mt][1]);
                s1 += expf(o[mt][nt][3] - gmax[mt][1]);
            }
            psum[mt][0] = s0;
            psum[mt][1] = s1;
        }
#pragma unroll
        for (int mt = 0; mt < 2; ++mt)
#pragma unroll
            for (int i = 0; i < 2; ++i) {
                float s = psum[mt][i];
                s += __shfl_xor_sync(0xffffffffu, s, 1);
                s += __shfl_xor_sync(0xffffffffu, s, 2);
                int r = m0 + mt * 16 + i * 8 + lq;
                sR2[r * 4 + wc] = s;
            }
        __syncthreads();

        // ---- lse + store
#pragma unroll
        for (int mt = 0; mt < 2; ++mt)
#pragma unroll
            for (int i = 0; i < 2; ++i) {
                int r = m0 + mt * 16 + i * 8 + lq;
                int grow = row0 + r;
                const float4 sv = *(const float4*)(sR2 + r * 4);
                float lse = gmax[mt][i] + logf(sv.x + sv.y + sv.z + sv.w);
                if (grow < N_NODES) {
                    float* dst = out + (size_t)grow * COUT + wc * 16 + 2 * lr;
#pragma unroll
                    for (int nt = 0; nt < 2; ++nt) {
                        float v0 = o[mt][nt][2 * i]     - lse;
                        float v1 = o[mt][nt][2 * i + 1] - lse;
                        *(float2*)(dst + nt * 8) = make_float2(v0, v1);
                    }
                }
            }
    }
}

extern "C" void kernel_launch(void* const* d_in, const int* in_sizes, int n_in,
                              void* d_out, int out_size)
{
    const float* x    = (const float*)d_in[0];
    // d_in[1] = neighbors (unused)
    const int*   mask = (const int*)d_in[2];
    const float* W1   = (const float*)d_in[3];
    const float* b1   = (const float*)d_in[4];
    const float* W2   = (const float*)d_in[5];
    const float* b2   = (const float*)d_in[6];
    float*       out  = (float*)d_out;

    cudaFuncSetAttribute(gcn_mma_kernel,
                         cudaFuncAttributeMaxDynamicSharedMemorySize, SMEM_BYTES);

    gcn_mma_kernel<<<GRID, THREADS, SMEM_BYTES>>>(x, mask, W1, b1, W2, b2, out);
}

// round 10
// speedup vs baseline: 3.7719x; 1.0405x over previous
#include <cuda_runtime.h>
#include <math.h>
#include <stdint.h>

// MultiStepUnitaryGCN collapses algebraically to a per-node MLP:
//   h   = relu(cos(sqrt(d)) * (x @ W1^T) + b1)
//   o   = cos(0.5*sqrt(d)) * (h @ W2^T) + b2
//   out = log_softmax(o, axis=1)
// (star-evolution weights are [cos(t*sqrt(d)),0,...]; neighbors unused;
//  nbr_mask arrives as int32 [N,16]).
//
// R9 -> R10: x tile back in smem; ALL tiles use a pair-packed layout where
// the mma.sync m16n8k8 fragment pair (k+lr, k+lr+4) is one contiguous 8B
// word -> every A/B fragment load is a single LDS.64. Kills the R9 LDG/cvt
// flood (L1 58%) in the hot loops.

#define N_NODES 50000
#define KNBR    16
#define CIN     128
#define CHID    128
#define COUT    64
#define TM      128
#define THREADS 512
#define NTILES  391
#define GRID    148
#define AS      132      // packed tile row stride (words)

// packed slot: row-major rows; per row, 16 k-groups of 8 words; word pair at
// (g*8 + lr*2) holds (val[k=8g+lr], val[k=8g+lr+4]).

// smem words:
//  sW1 [128*132]=16896  sW2 [64*132]=8448  sA [128*132]=16896 (x then h)
//  sC1[128] sC2[128] sB1[128] sB2[64] sR1[512] sR2[512]
#define SMEM_WORDS (16896 + 8448 + 16896 + 128 + 128 + 128 + 64 + 512 + 512)
#define SMEM_BYTES (SMEM_WORDS * 4)

__device__ __forceinline__ uint32_t f2tf(float f) {
    uint32_t u; asm("cvt.rna.tf32.f32 %0, %1;" : "=r"(u) : "f"(f)); return u;
}

__device__ __forceinline__ void mma8(float* d, uint2 aP0, uint2 aP1, uint2 bP) {
    asm volatile(
        "mma.sync.aligned.m16n8k8.row.col.f32.tf32.tf32.f32 "
        "{%0,%1,%2,%3}, {%4,%5,%6,%7}, {%8,%9}, {%0,%1,%2,%3};"
        : "+f"(d[0]), "+f"(d[1]), "+f"(d[2]), "+f"(d[3])
        : "r"(aP0.x), "r"(aP1.x), "r"(aP0.y), "r"(aP1.y),
          "r"(bP.x), "r"(bP.y));
}

__global__ void __launch_bounds__(THREADS, 1)
gcn_mma_kernel(const float* __restrict__ x, const int* __restrict__ mask,
               const float* __restrict__ W1, const float* __restrict__ b1,
               const float* __restrict__ W2, const float* __restrict__ b2,
               float* __restrict__ out)
{
    extern __shared__ uint32_t smem[];
    uint32_t* sW1 = smem;                       // 16896
    uint32_t* sW2 = smem + 16896;               // 8448
    uint32_t* sA  = smem + 25344;               // 16896 (x, then h)
    float*    sC1 = (float*)(smem + 42240);
    float*    sC2 = sC1 + 128;
    float*    sB1 = sC2 + 128;
    float*    sB2 = sB1 + 128;
    float*    sR1 = sB2 + 64;                   // 512: per-row per-wc max
    float*    sR2 = sR1 + 512;                  // 512: per-row per-wc sum

    const int tid  = threadIdx.x;
    const int lane = tid & 31;
    const int warp = tid >> 5;
    const int wr   = warp >> 2;                 // 0..3 row group
    const int wc   = warp & 3;                  // 0..3 col quarter
    const int m0   = wr * 32;
    const int lq   = lane >> 2;                 // 0..7
    const int lr   = lane & 3;                  // 0..3

    // ---- stage W1 packed (once)
    for (int idx = tid; idx < CHID * 16; idx += THREADS) {
        int c = idx >> 4, g = idx & 15;
        float4 v0 = *(const float4*)(W1 + c * CIN + g * 8);
        float4 v1 = *(const float4*)(W1 + c * CIN + g * 8 + 4);
        uint32_t* p = sW1 + c * AS + g * 8;
        *(uint2*)(p + 0) = make_uint2(f2tf(v0.x), f2tf(v1.x));
        *(uint2*)(p + 2) = make_uint2(f2tf(v0.y), f2tf(v1.y));
        *(uint2*)(p + 4) = make_uint2(f2tf(v0.z), f2tf(v1.z));
        *(uint2*)(p + 6) = make_uint2(f2tf(v0.w), f2tf(v1.w));
    }
    // ---- stage W2 packed (once)
    for (int idx = tid; idx < COUT * 16; idx += THREADS) {
        int c = idx >> 4, g = idx & 15;
        float4 v0 = *(const float4*)(W2 + c * CHID + g * 8);
        float4 v1 = *(const float4*)(W2 + c * CHID + g * 8 + 4);
        uint32_t* p = sW2 + c * AS + g * 8;
        *(uint2*)(p + 0) = make_uint2(f2tf(v0.x), f2tf(v1.x));
        *(uint2*)(p + 2) = make_uint2(f2tf(v0.y), f2tf(v1.y));
        *(uint2*)(p + 4) = make_uint2(f2tf(v0.z), f2tf(v1.z));
        *(uint2*)(p + 6) = make_uint2(f2tf(v0.w), f2tf(v1.w));
    }
    if (tid < CHID) sB1[tid] = b1[tid];
    if (tid < COUT) sB2[tid] = b2[tid];

    for (int tile = blockIdx.x; tile < NTILES; tile += GRID) {
        const int row0 = tile * TM;

        // ---- stage x tile packed (coalesced float4, tf32 once)
        for (int idx = tid; idx < TM * 16; idx += THREADS) {
            int r = idx >> 4, g = idx & 15;
            float4 v0 = make_float4(0.f, 0.f, 0.f, 0.f), v1 = v0;
            if (row0 + r < N_NODES) {
                v0 = *(const float4*)(x + (size_t)(row0 + r) * CIN + g * 8);
                v1 = *(const float4*)(x + (size_t)(row0 + r) * CIN + g * 8 + 4);
            }
            uint32_t* p = sA + r * AS + g * 8;
            *(uint2*)(p + 0) = make_uint2(f2tf(v0.x), f2tf(v1.x));
            *(uint2*)(p + 2) = make_uint2(f2tf(v0.y), f2tf(v1.y));
            *(uint2*)(p + 4) = make_uint2(f2tf(v0.z), f2tf(v1.z));
            *(uint2*)(p + 6) = make_uint2(f2tf(v0.w), f2tf(v1.w));
        }
        // ---- per-tile cos factors
        if (tid < TM) {
            int r = row0 + tid;
            float c1 = 0.f, c2 = 0.f;
            if (r < N_NODES) {
                const int4* mp = (const int4*)(mask + (size_t)r * KNBR);
                int4 a = mp[0], b = mp[1], c = mp[2], d4 = mp[3];
                int d = a.x + a.y + a.z + a.w + b.x + b.y + b.z + b.w
                      + c.x + c.y + c.z + c.w + d4.x + d4.y + d4.z + d4.w;
                float sd = sqrtf((float)d);
                c1 = cosf(sd);
                c2 = cosf(0.5f * sd);
            }
            sC1[tid] = c1;
            sC2[tid] = c2;
        }
        __syncthreads();

        // ---- GEMM1: 128x128 = X @ W1^T ; warp tile 32x32 ; all LDS.64
        float d1[2][4][4];
#pragma unroll
        for (int mt = 0; mt < 2; ++mt)
#pragma unroll
            for (int nt = 0; nt < 4; ++nt)
#pragma unroll
                for (int j = 0; j < 4; ++j) d1[mt][nt][j] = 0.f;

#pragma unroll 4
        for (int g = 0; g < 16; ++g) {
            const int go = g * 8 + lr * 2;
            uint2 a0[2], a1[2];
#pragma unroll
            for (int mt = 0; mt < 2; ++mt) {
                int r = m0 + mt * 16 + lq;
                a0[mt] = *(const uint2*)(sA + r * AS + go);
                a1[mt] = *(const uint2*)(sA + (r + 8) * AS + go);
            }
#pragma unroll
            for (int nt = 0; nt < 4; ++nt) {
                int col = wc * 32 + nt * 8 + lq;
                uint2 bP = *(const uint2*)(sW1 + col * AS + go);
                mma8(d1[0][nt], a0[0], a1[0], bP);
                mma8(d1[1][nt], a0[1], a1[1], bP);
            }
        }
        __syncthreads();   // all warps done reading x from sA

        // ---- epilogue1: h = relu(c1*d + b1) -> sA PACKED (scalar STS)
#pragma unroll
        for (int mt = 0; mt < 2; ++mt) {
            int r = m0 + mt * 16 + lq;
            float c1a = sC1[r], c1b = sC1[r + 8];
#pragma unroll
            for (int nt = 0; nt < 4; ++nt) {
                int c = wc * 32 + nt * 8 + 2 * lr;       // col, col+1
                float bx = sB1[c], by = sB1[c + 1];
                // packed positions for k=c and k=c+1 within group g2
                int g2 = wc * 4 + nt;
                int p0 = g2 * 8 + ((lr < 2) ? 4 * lr     : 4 * (lr - 2) + 1);
                int p1 = g2 * 8 + ((lr < 2) ? 4 * lr + 2 : 4 * (lr - 2) + 3);
                sA[r * AS + p0] = f2tf(fmaxf(fmaf(c1a, d1[mt][nt][0], bx), 0.f));
                sA[r * AS + p1] = f2tf(fmaxf(fmaf(c1a, d1[mt][nt][1], by), 0.f));
                sA[(r + 8) * AS + p0] = f2tf(fmaxf(fmaf(c1b, d1[mt][nt][2], bx), 0.f));
                sA[(r + 8) * AS + p1] = f2tf(fmaxf(fmaf(c1b, d1[mt][nt][3], by), 0.f));
            }
        }
        __syncthreads();

        // ---- GEMM2: 128x64 = H @ W2^T ; warp tile 32x16 ; all LDS.64
        float d2[2][2][4];
#pragma unroll
        for (int mt = 0; mt < 2; ++mt)
#pragma unroll
            for (int nt = 0; nt < 2; ++nt)
#pragma unroll
                for (int j = 0; j < 4; ++j) d2[mt][nt][j] = 0.f;

#pragma unroll 4
        for (int g = 0; g < 16; ++g) {
            const int go = g * 8 + lr * 2;
            uint2 a0[2], a1[2];
#pragma unroll
            for (int mt = 0; mt < 2; ++mt) {
                int r = m0 + mt * 16 + lq;
                a0[mt] = *(const uint2*)(sA + r * AS + go);
                a1[mt] = *(const uint2*)(sA + (r + 8) * AS + go);
            }
#pragma unroll
            for (int nt = 0; nt < 2; ++nt) {
                int col = wc * 16 + nt * 8 + lq;
                uint2 bP = *(const uint2*)(sW2 + col * AS + go);
                mma8(d2[0][nt], a0[0], a1[0], bP);
                mma8(d2[1][nt], a0[1], a1[1], bP);
            }
        }

        // ---- epilogue2: o = c2*d + b2 (regs) ; softmax partials
        float o[2][2][4];
        float rmax[2][2] = {{-1e30f, -1e30f}, {-1e30f, -1e30f}};
#pragma unroll
        for (int mt = 0; mt < 2; ++mt) {
            int r = m0 + mt * 16 + lq;
            float c2a = sC2[r], c2b = sC2[r + 8];
#pragma unroll
            for (int nt = 0; nt < 2; ++nt) {
                int c = wc * 16 + nt * 8 + 2 * lr;
                float bx = sB2[c], by = sB2[c + 1];
                o[mt][nt][0] = fmaf(c2a, d2[mt][nt][0], bx);
                o[mt][nt][1] = fmaf(c2a, d2[mt][nt][1], by);
                o[mt][nt][2] = fmaf(c2b, d2[mt][nt][2], bx);
                o[mt][nt][3] = fmaf(c2b, d2[mt][nt][3], by);
                rmax[mt][0] = fmaxf(rmax[mt][0], fmaxf(o[mt][nt][0], o[mt][nt][1]));
                rmax[mt][1] = fmaxf(rmax[mt][1], fmaxf(o[mt][nt][2], o[mt][nt][3]));
            }
        }
#pragma unroll
        for (int mt = 0; mt < 2; ++mt)
#pragma unroll
            for (int i = 0; i < 2; ++i) {
                float m = rmax[mt][i];
                m = fmaxf(m, __shfl_xor_sync(0xffffffffu, m, 1));
                m = fmaxf(m, __shfl_xor_sync(0xffffffffu, m, 2));
                int r = m0 + mt * 16 + i * 8 + lq;
                sR1[r * 4 + wc] = m;
            }
        __syncthreads();

        float gmax[2][2], psum[2][2];
#pragma unroll
        for (int mt = 0; mt < 2; ++mt)
#pragma unroll
            for (int i = 0; i < 2; ++i) {
                int r = m0 + mt * 16 + i * 8 + lq;
                const float4 mv = *(const float4*)(sR1 + r * 4);
                gmax[mt][i] = fmaxf(fmaxf(mv.x, mv.y), fmaxf(mv.z, mv.w));
            }
#pragma unroll
        for (int mt = 0; mt < 2; ++mt) {
            float s0 = 0.f, s1 = 0.f;
#pragma unroll
            for (int nt = 0; nt < 2; ++nt) {
                s0 += expf(o[mt][nt][0] - gmax[mt][0]);
                s0 += expf(o[mt][nt][1] - gmax[mt][0]);
                s1 += expf(o[mt][nt][2] - gmax[mt][1]);
                s1 += expf(o[mt][nt][3] - gmax[mt][1]);
            }
            psum[mt][0] = s0;
            psum[mt][1] = s1;
        }
#pragma unroll
        for (int mt = 0; mt < 2; ++mt)
#pragma unroll
            for (int i = 0; i < 2; ++i) {
                float s = psum[mt][i];
                s += __shfl_xor_sync(0xffffffffu, s, 1);
                s += __shfl_xor_sync(0xffffffffu, s, 2);
                int r = m0 + mt * 16 + i * 8 + lq;
                sR2[r * 4 + wc] = s;
            }
        __syncthreads();

        // ---- lse + store
#pragma unroll
        for (int mt = 0; mt < 2; ++mt)
#pragma unroll
            for (int i = 0; i < 2; ++i) {
                int r = m0 + mt * 16 + i * 8 + lq;
                int grow = row0 + r;
                const float4 sv = *(const float4*)(sR2 + r * 4);
                float lse = gmax[mt][i] + logf(sv.x + sv.y + sv.z + sv.w);
                if (grow < N_NODES) {
                    float* dst = out + (size_t)grow * COUT + wc * 16 + 2 * lr;
#pragma unroll
                    for (int nt = 0; nt < 2; ++nt) {
                        float v0 = o[mt][nt][2 * i]     - lse;
                        float v1 = o[mt][nt][2 * i + 1] - lse;
                        *(float2*)(dst + nt * 8) = make_float2(v0, v1);
                    }
                }
            }
    }
}

extern "C" void kernel_launch(void* const* d_in, const int* in_sizes, int n_in,
                              void* d_out, int out_size)
{
    const float* x    = (const float*)d_in[0];
    // d_in[1] = neighbors (unused)
    const int*   mask = (const int*)d_in[2];
    const float* W1   = (const float*)d_in[3];
    const float* b1   = (const float*)d_in[4];
    const float* W2   = (const float*)d_in[5];
    const float* b2   = (const float*)d_in[6];
    float*       out  = (float*)d_out;

    cudaFuncSetAttribute(gcn_mma_kernel,
                         cudaFuncAttributeMaxDynamicSharedMemorySize, SMEM_BYTES);

    gcn_mma_kernel<<<GRID, THREADS, SMEM_BYTES>>>(x, mask, W1, b1, W2, b2, out);
}

// round 11
// speedup vs baseline: 5.6760x; 1.5048x over previous
#include <cuda_runtime.h>
#include <math.h>
#include <stdint.h>

// MultiStepUnitaryGCN collapses algebraically to a per-node MLP:
//   h   = relu(cos(sqrt(d)) * (x @ W1^T) + b1)
//   o   = cos(0.5*sqrt(d)) * (h @ W2^T) + b2
//   out = log_softmax(o, axis=1)
// (star-evolution weights are [cos(t*sqrt(d)),0,...]; neighbors unused;
//  nbr_mask arrives as int32 [N,16]).
//
// R10 -> R11: AS 132 -> 136 (row stride ≡ 8 mod 32). Fragment-load bank
// starts become lq*8+lr*2: each 16-lane LDS.64 phase tiles the 32 banks
// perfectly -> ZERO bank conflicts on all GEMM A/B loads (R10 had 2-way).
// g-loops fully unrolled so LDS offsets fold to immediates.

#define N_NODES 50000
#define KNBR    16
#define CIN     128
#define CHID    128
#define COUT    64
#define TM      128
#define THREADS 512
#define NTILES  391
#define GRID    148
#define AS      136      // packed tile row stride (words), ≡8 mod 32

// packed slot: per row, 16 k-groups of 8 words; word pair at (g*8 + lr*2)
// holds (val[k=8g+lr], val[k=8g+lr+4]).

// smem words:
//  sW1 [128*136]=17408  sW2 [64*136]=8704  sA [128*136]=17408 (x then h)
//  sC1[128] sC2[128] sB1[128] sB2[64] sR1[512] sR2[512]
#define SMEM_WORDS (17408 + 8704 + 17408 + 128 + 128 + 128 + 64 + 512 + 512)
#define SMEM_BYTES (SMEM_WORDS * 4)

__device__ __forceinline__ uint32_t f2tf(float f) {
    uint32_t u; asm("cvt.rna.tf32.f32 %0, %1;" : "=r"(u) : "f"(f)); return u;
}

__device__ __forceinline__ void mma8(float* d, uint2 aP0, uint2 aP1, uint2 bP) {
    asm volatile(
        "mma.sync.aligned.m16n8k8.row.col.f32.tf32.tf32.f32 "
        "{%0,%1,%2,%3}, {%4,%5,%6,%7}, {%8,%9}, {%0,%1,%2,%3};"
        : "+f"(d[0]), "+f"(d[1]), "+f"(d[2]), "+f"(d[3])
        : "r"(aP0.x), "r"(aP1.x), "r"(aP0.y), "r"(aP1.y),
          "r"(bP.x), "r"(bP.y));
}

__global__ void __launch_bounds__(THREADS, 1)
gcn_mma_kernel(const float* __restrict__ x, const int* __restrict__ mask,
               const float* __restrict__ W1, const float* __restrict__ b1,
               const float* __restrict__ W2, const float* __restrict__ b2,
               float* __restrict__ out)
{
    extern __shared__ uint32_t smem[];
    uint32_t* sW1 = smem;                       // 17408
    uint32_t* sW2 = smem + 17408;               // 8704
    uint32_t* sA  = smem + 26112;               // 17408 (x, then h)
    float*    sC1 = (float*)(smem + 43520);
    float*    sC2 = sC1 + 128;
    float*    sB1 = sC2 + 128;
    float*    sB2 = sB1 + 128;
    float*    sR1 = sB2 + 64;                   // 512: per-row per-wc max
    float*    sR2 = sR1 + 512;                  // 512: per-row per-wc sum

    const int tid  = threadIdx.x;
    const int lane = tid & 31;
    const int warp = tid >> 5;
    const int wr   = warp >> 2;                 // 0..3 row group
    const int wc   = warp & 3;                  // 0..3 col quarter
    const int m0   = wr * 32;
    const int lq   = lane >> 2;                 // 0..7
    const int lr   = lane & 3;                  // 0..3

    // ---- stage W1 packed (once)
    for (int idx = tid; idx < CHID * 16; idx += THREADS) {
        int c = idx >> 4, g = idx & 15;
        float4 v0 = *(const float4*)(W1 + c * CIN + g * 8);
        float4 v1 = *(const float4*)(W1 + c * CIN + g * 8 + 4);
        uint32_t* p = sW1 + c * AS + g * 8;
        *(uint2*)(p + 0) = make_uint2(f2tf(v0.x), f2tf(v1.x));
        *(uint2*)(p + 2) = make_uint2(f2tf(v0.y), f2tf(v1.y));
        *(uint2*)(p + 4) = make_uint2(f2tf(v0.z), f2tf(v1.z));
        *(uint2*)(p + 6) = make_uint2(f2tf(v0.w), f2tf(v1.w));
    }
    // ---- stage W2 packed (once)
    for (int idx = tid; idx < COUT * 16; idx += THREADS) {
        int c = idx >> 4, g = idx & 15;
        float4 v0 = *(const float4*)(W2 + c * CHID + g * 8);
        float4 v1 = *(const float4*)(W2 + c * CHID + g * 8 + 4);
        uint32_t* p = sW2 + c * AS + g * 8;
        *(uint2*)(p + 0) = make_uint2(f2tf(v0.x), f2tf(v1.x));
        *(uint2*)(p + 2) = make_uint2(f2tf(v0.y), f2tf(v1.y));
        *(uint2*)(p + 4) = make_uint2(f2tf(v0.z), f2tf(v1.z));
        *(uint2*)(p + 6) = make_uint2(f2tf(v0.w), f2tf(v1.w));
    }
    if (tid < CHID) sB1[tid] = b1[tid];
    if (tid < COUT) sB2[tid] = b2[tid];

    for (int tile = blockIdx.x; tile < NTILES; tile += GRID) {
        const int row0 = tile * TM;

        // ---- stage x tile packed (coalesced float4, tf32 once)
        for (int idx = tid; idx < TM * 16; idx += THREADS) {
            int r = idx >> 4, g = idx & 15;
            float4 v0 = make_float4(0.f, 0.f, 0.f, 0.f), v1 = v0;
            if (row0 + r < N_NODES) {
                v0 = *(const float4*)(x + (size_t)(row0 + r) * CIN + g * 8);
                v1 = *(const float4*)(x + (size_t)(row0 + r) * CIN + g * 8 + 4);
            }
            uint32_t* p = sA + r * AS + g * 8;
            *(uint2*)(p + 0) = make_uint2(f2tf(v0.x), f2tf(v1.x));
            *(uint2*)(p + 2) = make_uint2(f2tf(v0.y), f2tf(v1.y));
            *(uint2*)(p + 4) = make_uint2(f2tf(v0.z), f2tf(v1.z));
            *(uint2*)(p + 6) = make_uint2(f2tf(v0.w), f2tf(v1.w));
        }
        // ---- per-tile cos factors
        if (tid < TM) {
            int r = row0 + tid;
            float c1 = 0.f, c2 = 0.f;
            if (r < N_NODES) {
                const int4* mp = (const int4*)(mask + (size_t)r * KNBR);
                int4 a = mp[0], b = mp[1], c = mp[2], d4 = mp[3];
                int d = a.x + a.y + a.z + a.w + b.x + b.y + b.z + b.w
                      + c.x + c.y + c.z + c.w + d4.x + d4.y + d4.z + d4.w;
                float sd = sqrtf((float)d);
                c1 = cosf(sd);
                c2 = cosf(0.5f * sd);
            }
            sC1[tid] = c1;
            sC2[tid] = c2;
        }
        __syncthreads();

        // ---- GEMM1: 128x128 = X @ W1^T ; warp tile 32x32 ; conflict-free LDS.64
        float d1[2][4][4];
#pragma unroll
        for (int mt = 0; mt < 2; ++mt)
#pragma unroll
            for (int nt = 0; nt < 4; ++nt)
#pragma unroll
                for (int j = 0; j < 4; ++j) d1[mt][nt][j] = 0.f;

#pragma unroll
        for (int g = 0; g < 16; ++g) {
            const int go = g * 8 + lr * 2;
            uint2 a0[2], a1[2];
#pragma unroll
            for (int mt = 0; mt < 2; ++mt) {
                int r = m0 + mt * 16 + lq;
                a0[mt] = *(const uint2*)(sA + r * AS + go);
                a1[mt] = *(const uint2*)(sA + (r + 8) * AS + go);
            }
#pragma unroll
            for (int nt = 0; nt < 4; ++nt) {
                int col = wc * 32 + nt * 8 + lq;
                uint2 bP = *(const uint2*)(sW1 + col * AS + go);
                mma8(d1[0][nt], a0[0], a1[0], bP);
                mma8(d1[1][nt], a0[1], a1[1], bP);
            }
        }
        __syncthreads();   // all warps done reading x from sA

        // ---- epilogue1: h = relu(c1*d + b1) -> sA PACKED (scalar STS)
#pragma unroll
        for (int mt = 0; mt < 2; ++mt) {
            int r = m0 + mt * 16 + lq;
            float c1a = sC1[r], c1b = sC1[r + 8];
#pragma unroll
            for (int nt = 0; nt < 4; ++nt) {
                int c = wc * 32 + nt * 8 + 2 * lr;       // col, col+1
                float bx = sB1[c], by = sB1[c + 1];
                int g2 = wc * 4 + nt;
                int p0 = g2 * 8 + ((lr < 2) ? 4 * lr     : 4 * (lr - 2) + 1);
                int p1 = g2 * 8 + ((lr < 2) ? 4 * lr + 2 : 4 * (lr - 2) + 3);
                sA[r * AS + p0] = f2tf(fmaxf(fmaf(c1a, d1[mt][nt][0], bx), 0.f));
                sA[r * AS + p1] = f2tf(fmaxf(fmaf(c1a, d1[mt][nt][1], by), 0.f));
                sA[(r + 8) * AS + p0] = f2tf(fmaxf(fmaf(c1b, d1[mt][nt][2], bx), 0.f));
                sA[(r + 8) * AS + p1] = f2tf(fmaxf(fmaf(c1b, d1[mt][nt][3], by), 0.f));
            }
        }
        __syncthreads();

        // ---- GEMM2: 128x64 = H @ W2^T ; warp tile 32x16 ; conflict-free LDS.64
        float d2[2][2][4];
#pragma unroll
        for (int mt = 0; mt < 2; ++mt)
#pragma unroll
            for (int nt = 0; nt < 2; ++nt)
#pragma unroll
                for (int j = 0; j < 4; ++j) d2[mt][nt][j] = 0.f;

#pragma unroll
        for (int g = 0; g < 16; ++g) {
            const int go = g * 8 + lr * 2;
            uint2 a0[2], a1[2];
#pragma unroll
            for (int mt = 0; mt < 2; ++mt) {
                int r = m0 + mt * 16 + lq;
                a0[mt] = *(const uint2*)(sA + r * AS + go);
                a1[mt] = *(const uint2*)(sA + (r + 8) * AS + go);
            }
#pragma unroll
            for (int nt = 0; nt < 2; ++nt) {
                int col = wc * 16 + nt * 8 + lq;
                uint2 bP = *(const uint2*)(sW2 + col * AS + go);
                mma8(d2[0][nt], a0[0], a1[0], bP);
                mma8(d2[1][nt], a0[1], a1[1], bP);
            }
        }

        // ---- epilogue2: o = c2*d + b2 (regs) ; softmax partials
        float o[2][2][4];
        float rmax[2][2] = {{-1e30f, -1e30f}, {-1e30f, -1e30f}};
#pragma unroll
        for (int mt = 0; mt < 2; ++mt) {
            int r = m0 + mt * 16 + lq;
            float c2a = sC2[r], c2b = sC2[r + 8];
#pragma unroll
            for (int nt = 0; nt < 2; ++nt) {
                int c = wc * 16 + nt * 8 + 2 * lr;
                float bx = sB2[c], by = sB2[c + 1];
                o[mt][nt][0] = fmaf(c2a, d2[mt][nt][0], bx);
                o[mt][nt][1] = fmaf(c2a, d2[mt][nt][1], by);
                o[mt][nt][2] = fmaf(c2b, d2[mt][nt][2], bx);
                o[mt][nt][3] = fmaf(c2b, d2[mt][nt][3], by);
                rmax[mt][0] = fmaxf(rmax[mt][0], fmaxf(o[mt][nt][0], o[mt][nt][1]));
                rmax[mt][1] = fmaxf(rmax[mt][1], fmaxf(o[mt][nt][2], o[mt][nt][3]));
            }
        }
#pragma unroll
        for (int mt = 0; mt < 2; ++mt)
#pragma unroll
            for (int i = 0; i < 2; ++i) {
                float m = rmax[mt][i];
                m = fmaxf(m, __shfl_xor_sync(0xffffffffu, m, 1));
                m = fmaxf(m, __shfl_xor_sync(0xffffffffu, m, 2));
                int r = m0 + mt * 16 + i * 8 + lq;
                sR1[r * 4 + wc] = m;
            }
        __syncthreads();

        float gmax[2][2], psum[2][2];
#pragma unroll
        for (int mt = 0; mt < 2; ++mt)
#pragma unroll
            for (int i = 0; i < 2; ++i) {
                int r = m0 + mt * 16 + i * 8 + lq;
                const float4 mv = *(const float4*)(sR1 + r * 4);
                gmax[mt][i] = fmaxf(fmaxf(mv.x, mv.y), fmaxf(mv.z, mv.w));
            }
#pragma unroll
        for (int mt = 0; mt < 2; ++mt) {
            float s0 = 0.f, s1 = 0.f;
#pragma unroll
            for (int nt = 0; nt < 2; ++nt) {
                s0 += expf(o[mt][nt][0] - gmax[mt][0]);
                s0 += expf(o[mt][nt][1] - gmax[mt][0]);
                s1 += expf(o[mt][nt][2] - gmax[mt][1]);
                s1 += expf(o[mt][nt][3] - gmax[mt][1]);
            }
            psum[mt][0] = s0;
            psum[mt][1] = s1;
        }
#pragma unroll
        for (int mt = 0; mt < 2; ++mt)
#pragma unroll
            for (int i = 0; i < 2; ++i) {
                float s = psum[mt][i];
                s += __shfl_xor_sync(0xffffffffu, s, 1);
                s += __shfl_xor_sync(0xffffffffu, s, 2);
                int r = m0 + mt * 16 + i * 8 + lq;
                sR2[r * 4 + wc] = s;
            }
        __syncthreads();

        // ---- lse + store
#pragma unroll
        for (int mt = 0; mt < 2; ++mt)
#pragma unroll
            for (int i = 0; i < 2; ++i) {
                int r = m0 + mt * 16 + i * 8 + lq;
                int grow = row0 + r;
                const float4 sv = *(const float4*)(sR2 + r * 4);
                float lse = gmax[mt][i] + logf(sv.x + sv.y + sv.z + sv.w);
                if (grow < N_NODES) {
                    float* dst = out + (size_t)grow * COUT + wc * 16 + 2 * lr;
#pragma unroll
                    for (int nt = 0; nt < 2; ++nt) {
                        float v0 = o[mt][nt][2 * i]     - lse;
                        float v1 = o[mt][nt][2 * i + 1] - lse;
                        *(float2*)(dst + nt * 8) = make_float2(v0, v1);
                    }
                }
            }
    }
}

extern "C" void kernel_launch(void* const* d_in, const int* in_sizes, int n_in,
                              void* d_out, int out_size)
{
    const float* x    = (const float*)d_in[0];
    // d_in[1] = neighbors (unused)
    const int*   mask = (const int*)d_in[2];
    const float* W1   = (const float*)d_in[3];
    const float* b1   = (const float*)d_in[4];
    const float* W2   = (const float*)d_in[5];
    const float* b2   = (const float*)d_in[6];
    float*       out  = (float*)d_out;

    cudaFuncSetAttribute(gcn_mma_kernel,
                         cudaFuncAttributeMaxDynamicSharedMemorySize, SMEM_BYTES);

    gcn_mma_kernel<<<GRID, THREADS, SMEM_BYTES>>>(x, mask, W1, b1, W2, b2, out);
}